// round 1
// baseline (speedup 1.0000x reference)
#include <cuda_runtime.h>
#include <cuda_bf16.h>

// Sparse conv: gather -> per-offset [P,32]x[32,32] GEMM -> scatter-add.
// Inputs (metadata order):
//   d_in[0] in_feature  float32 [N_VOX, 32]
//   d_in[1] kernel      float32 [K3, 32, 32]
//   d_in[2] bias        float32 [32]
//   d_in[3] nbmap       int32   [M, 2]   (src, dst), grouped by k, equal segments
//   d_in[4] nbsizes     int32   [K3]
// Output: float32 [N_VOX, 32]

#define CIN  32
#define COUT 32

__global__ void init_out_kernel(float* __restrict__ out,
                                const float* __restrict__ bias,
                                int n) {
    int i = blockIdx.x * blockDim.x + threadIdx.x;
    if (i < n) out[i] = bias[i & (COUT - 1)];
}

__global__ void __launch_bounds__(256)
sp_conv_kernel(const float* __restrict__ feat,
               const float* __restrict__ W,      // [K3, 32, 32]
               const int2* __restrict__ nbmap,   // [M] of (src,dst)
               float* __restrict__ out,
               int pairs_per_k) {
    // Per-block weight tile: all threads in this block share kernel offset k.
    __shared__ float4 sW[CIN * (COUT / 4)];   // 32 rows x 8 float4 = 4 KB

    const int k = blockIdx.y;
    {
        const float4* Wk = reinterpret_cast<const float4*>(W + (long)k * CIN * COUT);
        int t = threadIdx.x;
        if (t < CIN * (COUT / 4)) sW[t] = Wk[t];   // 256 float4 loads, one per thread
    }
    __syncthreads();

    const int p = blockIdx.x * blockDim.x + threadIdx.x;
    if (p >= pairs_per_k) return;

    const long m = (long)k * pairs_per_k + p;
    const int2 pair = nbmap[m];
    const int src = pair.x;
    const int dst = pair.y;

    // Gather: full 128B input row into registers.
    float x[CIN];
    {
        const float4* x4 = reinterpret_cast<const float4*>(feat) + (long)src * (CIN / 4);
#pragma unroll
        for (int j = 0; j < CIN / 4; j++) {
            float4 v = __ldg(&x4[j]);
            x[4 * j + 0] = v.x; x[4 * j + 1] = v.y;
            x[4 * j + 2] = v.z; x[4 * j + 3] = v.w;
        }
    }

    float acc[COUT];
#pragma unroll
    for (int o = 0; o < COUT; o++) acc[o] = 0.0f;

    // 32x32 FMA; weight LDS are warp-uniform broadcasts (conflict-free).
#pragma unroll
    for (int i = 0; i < CIN; i++) {
        const float xi = x[i];
#pragma unroll
        for (int j = 0; j < COUT / 4; j++) {
            float4 w = sW[i * (COUT / 4) + j];
            acc[4 * j + 0] += xi * w.x;
            acc[4 * j + 1] += xi * w.y;
            acc[4 * j + 2] += xi * w.z;
            acc[4 * j + 3] += xi * w.w;
        }
    }

    // Scatter-add: vector reductions (red.global.add.v4.f32, PTX ISA 8.1 / sm_90+).
    float* op = out + (long)dst * COUT;
#pragma unroll
    for (int j = 0; j < COUT / 4; j++) {
        asm volatile("red.global.add.v4.f32 [%0], {%1, %2, %3, %4};"
                     :: "l"(op + 4 * j),
                        "f"(acc[4 * j + 0]), "f"(acc[4 * j + 1]),
                        "f"(acc[4 * j + 2]), "f"(acc[4 * j + 3])
                     : "memory");
    }
}

extern "C" void kernel_launch(void* const* d_in, const int* in_sizes, int n_in,
                              void* d_out, int out_size) {
    const float* feat  = (const float*)d_in[0];
    const float* W     = (const float*)d_in[1];
    const float* bias  = (const float*)d_in[2];
    const int2*  nbmap = (const int2*)d_in[3];
    float* out = (float*)d_out;

    const int K3 = in_sizes[4];              // 27
    const int M  = in_sizes[3] / 2;          // total pairs
    const int pairs_per_k = M / K3;          // equal segments (reference assumes this)

    // 1) out = bias (broadcast); output was poisoned.
    {
        int n = out_size;
        int threads = 256;
        int blocks = (n + threads - 1) / threads;
        init_out_kernel<<<blocks, threads>>>(out, bias, n);
    }

    // 2) gather/GEMM/scatter-add.
    {
        dim3 block(256);
        dim3 grid((pairs_per_k + 255) / 256, K3);
        sp_conv_kernel<<<grid, block>>>(feat, W, nbmap, out, pairs_per_k);
    }
}

// round 2
// speedup vs baseline: 1.5744x; 1.5744x over previous
#include <cuda_runtime.h>
#include <cuda_bf16.h>

// Sparse conv: gather -> per-offset [P,32]x[32,32] GEMM -> scatter-add.
// Warp-cooperative layout: warp = 4 teams x 8 lanes. Team handles one pair per
// j-slot; lane c owns output channels [4c, 4c+4). Gather and scatter are fully
// coalesced (1 L1 wavefront per pair instead of 8), weight LDS amortized over
// 16 pairs per warp, x broadcast via shuffle (off the L1 crossbar).
//
// Inputs (metadata order):
//   d_in[0] in_feature  float32 [N_VOX, 32]
//   d_in[1] kernel      float32 [K3, 32, 32]
//   d_in[2] bias        float32 [32]
//   d_in[3] nbmap       int32   [M, 2]   (src, dst), grouped by k, equal segments
//   d_in[4] nbsizes     int32   [K3]
// Output: float32 [N_VOX, 32]

#define CIN  32
#define COUT 32
#define PAIRS_PER_WARP 16   // 4 j-slots x 4 teams

__global__ void init_out_kernel(float* __restrict__ out,
                                const float* __restrict__ bias,
                                int n) {
    int i = blockIdx.x * blockDim.x + threadIdx.x;
    if (i < n) out[i] = bias[i & (COUT - 1)];
}

__global__ void __launch_bounds__(256)
sp_conv_kernel(const float4* __restrict__ feat4,   // [N_VOX * 8] float4
               const float* __restrict__ W,        // [K3, 32, 32]
               const int2* __restrict__ nbmap,     // [M] of (src,dst)
               float* __restrict__ out,
               int pairs_per_k) {
    __shared__ float4 sW4[CIN * (COUT / 4)];       // 32 x 8 float4 = 4 KB

    const int k = blockIdx.y;
    const int t = threadIdx.x;

    // Stage this offset's 32x32 weight tile: 256 threads, one float4 each.
    {
        const float4* Wk4 = reinterpret_cast<const float4*>(W + (long)k * CIN * COUT);
        sW4[t] = Wk4[t];
    }
    __syncthreads();

    const int warp_id = t >> 5;
    const int lane    = t & 31;
    const int r       = lane >> 3;   // team 0..3 within warp
    const int c       = lane & 7;    // channel quad 0..7 within team

    const long base  = ((long)blockIdx.x * 8 + warp_id) * PAIRS_PER_WARP;
    const long gbase = (long)k * pairs_per_k + base;

    // Load 16 pairs' (src,dst) coalesced on lanes 0..15.
    int2 mypair = make_int2(0, 0);
    if (lane < PAIRS_PER_WARP && base + lane < pairs_per_k)
        mypair = nbmap[gbase + lane];

    int  src[4], dst[4];
    bool valid[4];
#pragma unroll
    for (int j = 0; j < 4; j++) {
        const int idx = j * 4 + r;   // pair slot within the warp's 16
        src[j]   = __shfl_sync(0xffffffffu, mypair.x, idx, 32);
        dst[j]   = __shfl_sync(0xffffffffu, mypair.y, idx, 32);
        valid[j] = (base + idx) < pairs_per_k;
    }

    // Coalesced gather: per j, the warp's 32 lanes cover 4 rows x 128B.
    float xr[4][4];
#pragma unroll
    for (int j = 0; j < 4; j++) {
        float4 v = valid[j] ? __ldg(&feat4[(long)src[j] * (CIN / 4) + c])
                            : make_float4(0.f, 0.f, 0.f, 0.f);
        xr[j][0] = v.x; xr[j][1] = v.y; xr[j][2] = v.z; xr[j][3] = v.w;
    }

    float4 acc[4];
#pragma unroll
    for (int j = 0; j < 4; j++) acc[j] = make_float4(0.f, 0.f, 0.f, 0.f);

    // 32 input channels: i = cp*4 + q, x[p][i] lives in team-lane cp, comp q.
#pragma unroll
    for (int cp = 0; cp < 8; cp++) {
#pragma unroll
        for (int q = 0; q < 4; q++) {
            const int i = cp * 4 + q;
            const float4 w = sW4[i * (COUT / 4) + c];   // broadcast across teams
#pragma unroll
            for (int j = 0; j < 4; j++) {
                const float xi = __shfl_sync(0xffffffffu, xr[j][q], cp, 8);
                acc[j].x += xi * w.x;
                acc[j].y += xi * w.y;
                acc[j].z += xi * w.z;
                acc[j].w += xi * w.w;
            }
        }
    }

    // Coalesced scatter-add: per j, 32 lanes cover 4 output rows x 128B.
#pragma unroll
    for (int j = 0; j < 4; j++) {
        if (valid[j]) {
            float* op = out + (long)dst[j] * COUT + c * 4;
            asm volatile("red.global.add.v4.f32 [%0], {%1, %2, %3, %4};"
                         :: "l"(op),
                            "f"(acc[j].x), "f"(acc[j].y),
                            "f"(acc[j].z), "f"(acc[j].w)
                         : "memory");
        }
    }
}

extern "C" void kernel_launch(void* const* d_in, const int* in_sizes, int n_in,
                              void* d_out, int out_size) {
    const float4* feat4 = (const float4*)d_in[0];
    const float*  W     = (const float*)d_in[1];
    const float*  bias  = (const float*)d_in[2];
    const int2*   nbmap = (const int2*)d_in[3];
    float* out = (float*)d_out;

    const int K3 = in_sizes[4];              // 27
    const int M  = in_sizes[3] / 2;          // total pairs
    const int pairs_per_k = M / K3;          // equal segments

    // 1) out = bias (output buffer is poisoned).
    {
        int n = out_size;
        int threads = 256;
        int blocks = (n + threads - 1) / threads;
        init_out_kernel<<<blocks, threads>>>(out, bias, n);
    }

    // 2) gather / per-offset GEMM / scatter-add.
    {
        const int pairs_per_block = 8 * PAIRS_PER_WARP;  // 8 warps
        dim3 block(256);
        dim3 grid((pairs_per_k + pairs_per_block - 1) / pairs_per_block, K3);
        sp_conv_kernel<<<grid, block>>>(feat4, W, nbmap, out, pairs_per_k);
    }
}